// round 1
// baseline (speedup 1.0000x reference)
#include <cuda_runtime.h>
#include <math.h>

#define B_    2
#define T_    2048
#define D_    1024
#define H_    16
#define HD_   64
#define WIN_  512
#define ROWS_ (B_*T_)   // 4096

// Scratch (device globals: allowed; runtime allocs are not)
__device__ float g_q [B_*T_*D_];
__device__ float g_k [B_*T_*D_];
__device__ float g_v [B_*T_*D_];
__device__ float g_ao[B_*T_*D_];

// ---------------------------------------------------------------------------
// C[M,N] = A[M,K] @ W[N,K]^T   (fp32 SIMT, 128x128x16 tiles, 8x8 microtile)
// ---------------------------------------------------------------------------
__global__ __launch_bounds__(256) void gemm_nt(const float* __restrict__ A,
                                               const float* __restrict__ W,
                                               float* __restrict__ C,
                                               int M, int N, int K)
{
    __shared__ float As[16][132];   // [k][m], padded
    __shared__ float Bs[16][132];   // [k][n], padded
    const int tid = threadIdx.x;
    const int tx  = tid & 15;
    const int ty  = tid >> 4;
    const int m0  = blockIdx.y * 128;
    const int n0  = blockIdx.x * 128;
    const int lr  = tid >> 1;           // 0..127 tile row
    const int lc0 = (tid & 1) * 8;      // k offset base

    float acc[8][8];
#pragma unroll
    for (int i = 0; i < 8; i++)
#pragma unroll
        for (int j = 0; j < 8; j++) acc[i][j] = 0.f;

    for (int k0 = 0; k0 < K; k0 += 16) {
#pragma unroll
        for (int it = 0; it < 2; it++) {
            int kk = lc0 + it * 4;
            float4 va = *(const float4*)(A + (size_t)(m0 + lr) * K + k0 + kk);
            As[kk+0][lr] = va.x; As[kk+1][lr] = va.y;
            As[kk+2][lr] = va.z; As[kk+3][lr] = va.w;
            float4 vb = *(const float4*)(W + (size_t)(n0 + lr) * K + k0 + kk);
            Bs[kk+0][lr] = vb.x; Bs[kk+1][lr] = vb.y;
            Bs[kk+2][lr] = vb.z; Bs[kk+3][lr] = vb.w;
        }
        __syncthreads();
#pragma unroll
        for (int k = 0; k < 16; k++) {
            float a[8], b[8];
            *(float4*)(a)     = *(const float4*)&As[k][ty*8];
            *(float4*)(a + 4) = *(const float4*)&As[k][ty*8 + 4];
            *(float4*)(b)     = *(const float4*)&Bs[k][tx*8];
            *(float4*)(b + 4) = *(const float4*)&Bs[k][tx*8 + 4];
#pragma unroll
            for (int i = 0; i < 8; i++)
#pragma unroll
                for (int j = 0; j < 8; j++)
                    acc[i][j] = fmaf(a[i], b[j], acc[i][j]);
        }
        __syncthreads();
    }
#pragma unroll
    for (int i = 0; i < 8; i++) {
        float* cp = C + (size_t)(m0 + ty*8 + i) * N + n0 + tx*8;
        *(float4*)(cp)     = make_float4(acc[i][0], acc[i][1], acc[i][2], acc[i][3]);
        *(float4*)(cp + 4) = make_float4(acc[i][4], acc[i][5], acc[i][6], acc[i][7]);
    }
}

// ---------------------------------------------------------------------------
// RMSNorm over full 1024-dim rows of g_q (y=0) / g_k (y=1), in place.
// ---------------------------------------------------------------------------
__global__ __launch_bounds__(256) void rmsnorm_k(const float* __restrict__ wq,
                                                 const float* __restrict__ wk)
{
    const int row = blockIdx.x;
    float* x        = blockIdx.y ? g_k : g_q;
    const float* w  = blockIdx.y ? wk  : wq;
    float4* xp = (float4*)(x + (size_t)row * D_);
    float4 v = xp[threadIdx.x];
    float ss = v.x*v.x + v.y*v.y + v.z*v.z + v.w*v.w;
#pragma unroll
    for (int o = 16; o > 0; o >>= 1) ss += __shfl_xor_sync(0xffffffffu, ss, o);
    __shared__ float red[8];
    if ((threadIdx.x & 31) == 0) red[threadIdx.x >> 5] = ss;
    __syncthreads();
    float tot = red[0]+red[1]+red[2]+red[3]+red[4]+red[5]+red[6]+red[7];
    float inv = rsqrtf(tot * (1.f / D_) + 1e-6f);
    float4 wv = ((const float4*)w)[threadIdx.x];
    v.x *= inv * wv.x; v.y *= inv * wv.y; v.z *= inv * wv.z; v.w *= inv * wv.w;
    xp[threadIdx.x] = v;
}

// ---------------------------------------------------------------------------
// Flash-style windowed causal attention with ALiBi.
// grid = (T/64 query tiles, B*H). 64x64 tiles, 4x4 microtile per thread.
// ---------------------------------------------------------------------------
__global__ __launch_bounds__(256) void attn_k()
{
    __shared__ float Qs[64][64];   // [d][m]
    __shared__ float KP[64][64];   // phase 1: K as [d][n]; phase 2: P as [r][c]
    __shared__ float Vs[64][64];   // [n][d]

    const int tid = threadIdx.x;
    const int tx  = tid & 15;
    const int ty  = tid >> 4;
    const int bh  = blockIdx.y;
    const int b   = bh >> 4;
    const int h   = bh & 15;
    const int m0  = blockIdx.x * 64;
    const float slope = exp2f(-0.5f * (float)(h + 1));
    const float scale = 0.125f;   // HD^-0.5
    const size_t base = ((size_t)b * T_) * D_ + (size_t)h * HD_;

    // Load Q tile transposed: Qs[d][m]
    {
        const int m  = tid >> 2;
        const int q4 = tid & 3;
#pragma unroll
        for (int it = 0; it < 4; it++) {
            int d0 = q4 * 16 + it * 4;
            float4 v = *(const float4*)(g_q + base + (size_t)(m0 + m) * D_ + d0);
            Qs[d0+0][m] = v.x; Qs[d0+1][m] = v.y;
            Qs[d0+2][m] = v.z; Qs[d0+3][m] = v.w;
        }
    }

    float acc[4][4];
    float mrow[4], lrow[4];
#pragma unroll
    for (int i = 0; i < 4; i++) {
        mrow[i] = -1e30f; lrow[i] = 0.f;
#pragma unroll
        for (int j = 0; j < 4; j++) acc[i][j] = 0.f;
    }

    const int jb0 = max(0, m0 - WIN_) >> 6;
    const int jb1 = m0 >> 6;

    for (int jb = jb0; jb <= jb1; jb++) {
        const int n0 = jb << 6;
        __syncthreads();   // previous-iter PV done reading KP/Vs
        {
            const int n  = tid >> 2;
            const int q4 = tid & 3;
#pragma unroll
            for (int it = 0; it < 4; it++) {
                int d0 = q4 * 16 + it * 4;
                float4 kv = *(const float4*)(g_k + base + (size_t)(n0 + n) * D_ + d0);
                KP[d0+0][n] = kv.x; KP[d0+1][n] = kv.y;
                KP[d0+2][n] = kv.z; KP[d0+3][n] = kv.w;
                float4 vv = *(const float4*)(g_v + base + (size_t)(n0 + n) * D_ + d0);
                *(float4*)&Vs[n][d0] = vv;
            }
        }
        __syncthreads();

        // S = Q K^T
        float s[4][4];
#pragma unroll
        for (int i = 0; i < 4; i++)
#pragma unroll
            for (int j = 0; j < 4; j++) s[i][j] = 0.f;
#pragma unroll 8
        for (int d = 0; d < 64; d++) {
            float4 qf = *(const float4*)&Qs[d][ty*4];
            float4 kf = *(const float4*)&KP[d][tx*4];
            const float qa[4] = {qf.x, qf.y, qf.z, qf.w};
            const float ka[4] = {kf.x, kf.y, kf.z, kf.w};
#pragma unroll
            for (int i = 0; i < 4; i++)
#pragma unroll
                for (int j = 0; j < 4; j++)
                    s[i][j] = fmaf(qa[i], ka[j], s[i][j]);
        }
        __syncthreads();   // done reading KP; safe to overwrite with P

        // scale + ALiBi + mask + online softmax
        float p[4][4];
#pragma unroll
        for (int i = 0; i < 4; i++) {
            const int r = m0 + ty*4 + i;
            float sv[4];
            float rm = -1e30f;
#pragma unroll
            for (int j = 0; j < 4; j++) {
                const int c = n0 + tx*4 + j;
                float val = s[i][j] * scale + slope * (float)(c - r);
                bool valid = (c <= r) && (c >= r - WIN_);
                sv[j] = valid ? val : -1e30f;
                rm = fmaxf(rm, sv[j]);
            }
#pragma unroll
            for (int o = 1; o < 16; o <<= 1)
                rm = fmaxf(rm, __shfl_xor_sync(0xffffffffu, rm, o));
            const float nm    = fmaxf(mrow[i], rm);
            const float alpha = __expf(mrow[i] - nm);
            float rs = 0.f;
#pragma unroll
            for (int j = 0; j < 4; j++) {
                float pv = (sv[j] > -1e29f) ? __expf(sv[j] - nm) : 0.f;
                p[i][j] = pv; rs += pv;
            }
#pragma unroll
            for (int o = 1; o < 16; o <<= 1)
                rs += __shfl_xor_sync(0xffffffffu, rs, o);
            lrow[i] = lrow[i] * alpha + rs;
            mrow[i] = nm;
#pragma unroll
            for (int j = 0; j < 4; j++) acc[i][j] *= alpha;
        }

        // store P row-major into KP: P[r][c]
#pragma unroll
        for (int i = 0; i < 4; i++)
            *(float4*)&KP[ty*4 + i][tx*4] =
                make_float4(p[i][0], p[i][1], p[i][2], p[i][3]);
        __syncthreads();

        // O += P V
        for (int c0 = 0; c0 < 64; c0 += 4) {
            float4 pf[4], vf[4];
#pragma unroll
            for (int i = 0; i < 4; i++)  pf[i] = *(const float4*)&KP[ty*4 + i][c0];
#pragma unroll
            for (int cc = 0; cc < 4; cc++) vf[cc] = *(const float4*)&Vs[c0 + cc][tx*4];
#pragma unroll
            for (int i = 0; i < 4; i++) {
                const float pa[4] = {pf[i].x, pf[i].y, pf[i].z, pf[i].w};
#pragma unroll
                for (int cc = 0; cc < 4; cc++) {
                    const float va[4] = {vf[cc].x, vf[cc].y, vf[cc].z, vf[cc].w};
#pragma unroll
                    for (int j = 0; j < 4; j++)
                        acc[i][j] = fmaf(pa[cc], va[j], acc[i][j]);
                }
            }
        }
    }

    // epilogue: normalize and write [B,T,H*HD]
#pragma unroll
    for (int i = 0; i < 4; i++) {
        const float inv = 1.f / lrow[i];
        float* op = g_ao + base + (size_t)(m0 + ty*4 + i) * D_ + tx*4;
        *(float4*)op = make_float4(acc[i][0]*inv, acc[i][1]*inv,
                                   acc[i][2]*inv, acc[i][3]*inv);
    }
}

// ---------------------------------------------------------------------------
extern "C" void kernel_launch(void* const* d_in, const int* in_sizes, int n_in,
                              void* d_out, int out_size)
{
    const float* x  = (const float*)d_in[0];
    const float* wq = (const float*)d_in[1];
    const float* wk = (const float*)d_in[2];
    const float* wv = (const float*)d_in[3];
    const float* wo = (const float*)d_in[4];
    const float* qw = (const float*)d_in[5];
    const float* kw = (const float*)d_in[6];
    float* out = (float*)d_out;

    float *q, *k, *v, *ao;
    cudaGetSymbolAddress((void**)&q,  g_q);
    cudaGetSymbolAddress((void**)&k,  g_k);
    cudaGetSymbolAddress((void**)&v,  g_v);
    cudaGetSymbolAddress((void**)&ao, g_ao);

    dim3 gg(D_ / 128, ROWS_ / 128);   // (8, 32)
    gemm_nt<<<gg, 256>>>(x, wq, q, ROWS_, D_, D_);
    gemm_nt<<<gg, 256>>>(x, wk, k, ROWS_, D_, D_);
    gemm_nt<<<gg, 256>>>(x, wv, v, ROWS_, D_, D_);
    rmsnorm_k<<<dim3(ROWS_, 2), 256>>>(qw, kw);
    attn_k<<<dim3(T_ / 64, B_ * H_), 256>>>();
    gemm_nt<<<gg, 256>>>(ao, wo, out, ROWS_, D_, D_);
}

// round 3
// speedup vs baseline: 1.7989x; 1.7989x over previous
#include <cuda_runtime.h>
#include <cuda_bf16.h>
#include <math.h>
#include <stdint.h>

#define B_    2
#define T_    2048
#define D_    1024
#define H_    16
#define HD_   64
#define WIN_  512
#define ROWS_ (B_*T_)   // 4096

// ---------------- scratch (device globals; no runtime alloc) ----------------
__device__ float g_q [B_*T_*D_];
__device__ float g_k [B_*T_*D_];
__device__ float g_v [B_*T_*D_];
__device__ float g_ao[B_*T_*D_];
__device__ __nv_bfloat16 g_xhi [B_*T_*D_];
__device__ __nv_bfloat16 g_xlo [B_*T_*D_];
__device__ __nv_bfloat16 g_aohi[B_*T_*D_];
__device__ __nv_bfloat16 g_aolo[B_*T_*D_];
__device__ __nv_bfloat16 g_whi [4 * D_ * D_];
__device__ __nv_bfloat16 g_wlo [4 * D_ * D_];

__device__ __forceinline__ uint32_t smem_to_u32(const void* p) {
    uint32_t a;
    asm("{ .reg .u64 t; cvta.to.shared.u64 t, %1; cvt.u32.u64 %0, t; }"
        : "=r"(a) : "l"(p));
    return a;
}

#define LDSM4(r, addr) \
    asm volatile("ldmatrix.sync.aligned.m8n8.x4.shared.b16 {%0,%1,%2,%3}, [%4];" \
        : "=r"((r)[0]), "=r"((r)[1]), "=r"((r)[2]), "=r"((r)[3]) : "r"(addr))

#define MMA_BF16(c, a, b0, b1) \
    asm volatile("mma.sync.aligned.m16n8k16.row.col.f32.bf16.bf16.f32 " \
        "{%0,%1,%2,%3}, {%4,%5,%6,%7}, {%8,%9}, {%0,%1,%2,%3};" \
        : "+f"((c)[0]), "+f"((c)[1]), "+f"((c)[2]), "+f"((c)[3]) \
        : "r"((a)[0]), "r"((a)[1]), "r"((a)[2]), "r"((a)[3]), "r"(b0), "r"(b1))

#define CP_ASYNC16(sa, gp) \
    asm volatile("cp.async.cg.shared.global [%0], [%1], 16;\n" :: "r"(sa), "l"(gp))
#define CP_COMMIT()  asm volatile("cp.async.commit_group;\n" ::: "memory")
#define CP_WAIT(n)   asm volatile("cp.async.wait_group %0;\n" :: "n"(n) : "memory")

// ---------------------------------------------------------------------------
// fp32 -> (bf16 hi, bf16 lo) split. 8 elements/thread, vectorized.
// ---------------------------------------------------------------------------
__global__ __launch_bounds__(256) void cvt_split(const float* __restrict__ in,
                                                 __nv_bfloat16* __restrict__ hi,
                                                 __nv_bfloat16* __restrict__ lo,
                                                 int n8)
{
    int u = blockIdx.x * 256 + threadIdx.x;
    if (u >= n8) return;
    const float4* p = (const float4*)in + (size_t)u * 2;
    float4 a = p[0], b = p[1];
    float f[8] = {a.x, a.y, a.z, a.w, b.x, b.y, b.z, b.w};
    union { __nv_bfloat16 h[8]; uint4 u4; } ph, pl;
#pragma unroll
    for (int j = 0; j < 8; j++) {
        __nv_bfloat16 h = __float2bfloat16_rn(f[j]);
        float r = f[j] - __bfloat162float(h);
        ph.h[j] = h;
        pl.h[j] = __float2bfloat16_rn(r);
    }
    *(uint4*)(hi + (size_t)u * 8) = ph.u4;
    *(uint4*)(lo + (size_t)u * 8) = pl.u4;
}

// ---------------------------------------------------------------------------
// HMMA bf16 split GEMM: C[M,N] f32 = (Ahi+Alo)[M,K] @ (Whi+Wlo)[N,K]^T
// 128x128 CTA tile, 8 warps x (64x32), K-chunk 32, cp.async double buffer.
// smem per stage: 4 tiles (Ahi,Alo,Whi,Wlo), 128 rows x 80B (32bf16 + pad).
// ---------------------------------------------------------------------------
#define TILE_B   10240          // 128 * 80
#define STAGE_B  40960          // 4 tiles
#define GEMM_SMEM (2 * STAGE_B) // 81920

__global__ __launch_bounds__(256) void gemm_hmma(
    const __nv_bfloat16* __restrict__ Ahi, const __nv_bfloat16* __restrict__ Alo,
    const __nv_bfloat16* __restrict__ Whi, const __nv_bfloat16* __restrict__ Wlo,
    float* __restrict__ C, int M, int N, int K)
{
    extern __shared__ char smem[];
    const uint32_t sb = smem_to_u32(smem);
    const int tid  = threadIdx.x;
    const int lane = tid & 31;
    const int wid  = tid >> 5;
    const int wm   = (wid & 1) * 64;    // warp M offset in tile
    const int wn   = (wid >> 1) * 32;   // warp N offset in tile
    const int m0   = blockIdx.y * 128;
    const int n0   = blockIdx.x * 128;
    const int NCH  = K >> 5;            // 32-wide K chunks

    const __nv_bfloat16* srcs[4] = {Ahi, Alo, Whi, Wlo};

    // ---- async fill of one stage with chunk ch ----
    auto issue = [&](int ch, int stg) {
        const int k0 = ch << 5;
        const uint32_t base = sb + (uint32_t)stg * STAGE_B;
#pragma unroll
        for (int t = 0; t < 4; t++) {
            const __nv_bfloat16* src = srcs[t];
            const int rb = (t < 2) ? m0 : n0;
#pragma unroll
            for (int it = 0; it < 2; it++) {
                const int u   = tid + it * 256;
                const int row = u >> 2;
                const int kq  = (u & 3) * 8;
                const uint32_t sa = base + (uint32_t)(t * TILE_B + row * 80 + kq * 2);
                const __nv_bfloat16* gp = src + (size_t)(rb + row) * K + k0 + kq;
                CP_ASYNC16(sa, gp);
            }
        }
        CP_COMMIT();
    };

    float acc[4][4][4];
#pragma unroll
    for (int mt = 0; mt < 4; mt++)
#pragma unroll
        for (int nt = 0; nt < 4; nt++)
#pragma unroll
            for (int e = 0; e < 4; e++) acc[mt][nt][e] = 0.f;

    issue(0, 0);

    for (int i = 0; i < NCH; i++) {
        if (i + 1 < NCH) { issue(i + 1, (i + 1) & 1); CP_WAIT(1); }
        else             { CP_WAIT(0); }
        __syncthreads();

        const uint32_t base = sb + (uint32_t)(i & 1) * STAGE_B;
        const uint32_t aH = base, aL = base + TILE_B;
        const uint32_t wH = base + 2 * TILE_B, wL = base + 3 * TILE_B;

#pragma unroll
        for (int ks = 0; ks < 2; ks++) {
            const int kb = ks * 16;
            uint32_t ah[4][4], al[4][4], bh[2][4], bl[2][4];
            const uint32_t aOff = (uint32_t)((wm + (lane & 15)) * 80
                                             + (kb + (lane >> 4) * 8) * 2);
#pragma unroll
            for (int mt = 0; mt < 4; mt++) {
                LDSM4(ah[mt], aH + aOff + mt * 16 * 80);
                LDSM4(al[mt], aL + aOff + mt * 16 * 80);
            }
            const uint32_t bOff = (uint32_t)((wn + ((lane >> 4) * 8) + (lane & 7)) * 80
                                             + (kb + ((lane >> 3) & 1) * 8) * 2);
#pragma unroll
            for (int p = 0; p < 2; p++) {
                LDSM4(bh[p], wH + bOff + p * 16 * 80);
                LDSM4(bl[p], wL + bOff + p * 16 * 80);
            }
#pragma unroll
            for (int mt = 0; mt < 4; mt++)
#pragma unroll
                for (int nt = 0; nt < 4; nt++) {
                    const int p = nt >> 1, s = (nt & 1) * 2;
                    MMA_BF16(acc[mt][nt], ah[mt], bh[p][s], bh[p][s + 1]);
                    MMA_BF16(acc[mt][nt], ah[mt], bl[p][s], bl[p][s + 1]);
                    MMA_BF16(acc[mt][nt], al[mt], bh[p][s], bh[p][s + 1]);
                }
        }
        __syncthreads();
    }

    // epilogue: fragment -> C
#pragma unroll
    for (int mt = 0; mt < 4; mt++)
#pragma unroll
        for (int nt = 0; nt < 4; nt++) {
            const int r = m0 + wm + mt * 16 + (lane >> 2);
            const int c = n0 + wn + nt * 8 + (lane & 3) * 2;
            *(float2*)(C + (size_t)r * N + c) =
                make_float2(acc[mt][nt][0], acc[mt][nt][1]);
            *(float2*)(C + (size_t)(r + 8) * N + c) =
                make_float2(acc[mt][nt][2], acc[mt][nt][3]);
        }
}

// ---------------------------------------------------------------------------
// RMSNorm over full 1024-dim rows of g_q (y=0) / g_k (y=1), in place.
// ---------------------------------------------------------------------------
__global__ __launch_bounds__(256) void rmsnorm_k(const float* __restrict__ wq,
                                                 const float* __restrict__ wk)
{
    const int row = blockIdx.x;
    float* x        = blockIdx.y ? g_k : g_q;
    const float* w  = blockIdx.y ? wk  : wq;
    float4* xp = (float4*)(x + (size_t)row * D_);
    float4 v = xp[threadIdx.x];
    float ss = v.x*v.x + v.y*v.y + v.z*v.z + v.w*v.w;
#pragma unroll
    for (int o = 16; o > 0; o >>= 1) ss += __shfl_xor_sync(0xffffffffu, ss, o);
    __shared__ float red[8];
    if ((threadIdx.x & 31) == 0) red[threadIdx.x >> 5] = ss;
    __syncthreads();
    float tot = red[0]+red[1]+red[2]+red[3]+red[4]+red[5]+red[6]+red[7];
    float inv = rsqrtf(tot * (1.f / D_) + 1e-6f);
    float4 wv = ((const float4*)w)[threadIdx.x];
    v.x *= inv * wv.x; v.y *= inv * wv.y; v.z *= inv * wv.z; v.w *= inv * wv.w;
    xp[threadIdx.x] = v;
}

// ---------------------------------------------------------------------------
// Flash-style windowed causal attention with ALiBi (fp32 SIMT).
// ---------------------------------------------------------------------------
__global__ __launch_bounds__(256) void attn_k()
{
    __shared__ float Qs[64][64];
    __shared__ float KP[64][64];
    __shared__ float Vs[64][64];

    const int tid = threadIdx.x;
    const int tx  = tid & 15;
    const int ty  = tid >> 4;
    const int bh  = blockIdx.y;
    const int b   = bh >> 4;
    const int h   = bh & 15;
    const int m0  = blockIdx.x * 64;
    const float slope = exp2f(-0.5f * (float)(h + 1));
    const float scale = 0.125f;
    const size_t base = ((size_t)b * T_) * D_ + (size_t)h * HD_;

    {
        const int m  = tid >> 2;
        const int q4 = tid & 3;
#pragma unroll
        for (int it = 0; it < 4; it++) {
            int d0 = q4 * 16 + it * 4;
            float4 v = *(const float4*)(g_q + base + (size_t)(m0 + m) * D_ + d0);
            Qs[d0+0][m] = v.x; Qs[d0+1][m] = v.y;
            Qs[d0+2][m] = v.z; Qs[d0+3][m] = v.w;
        }
    }

    float acc[4][4];
    float mrow[4], lrow[4];
#pragma unroll
    for (int i = 0; i < 4; i++) {
        mrow[i] = -1e30f; lrow[i] = 0.f;
#pragma unroll
        for (int j = 0; j < 4; j++) acc[i][j] = 0.f;
    }

    const int jb0 = max(0, m0 - WIN_) >> 6;
    const int jb1 = m0 >> 6;

    for (int jb = jb0; jb <= jb1; jb++) {
        const int n0 = jb << 6;
        __syncthreads();
        {
            const int n  = tid >> 2;
            const int q4 = tid & 3;
#pragma unroll
            for (int it = 0; it < 4; it++) {
                int d0 = q4 * 16 + it * 4;
                float4 kv = *(const float4*)(g_k + base + (size_t)(n0 + n) * D_ + d0);
                KP[d0+0][n] = kv.x; KP[d0+1][n] = kv.y;
                KP[d0+2][n] = kv.z; KP[d0+3][n] = kv.w;
                float4 vv = *(const float4*)(g_v + base + (size_t)(n0 + n) * D_ + d0);
                *(float4*)&Vs[n][d0] = vv;
            }
        }
        __syncthreads();

        float s[4][4];
#pragma unroll
        for (int i = 0; i < 4; i++)
#pragma unroll
            for (int j = 0; j < 4; j++) s[i][j] = 0.f;
#pragma unroll 8
        for (int d = 0; d < 64; d++) {
            float4 qf = *(const float4*)&Qs[d][ty*4];
            float4 kf = *(const float4*)&KP[d][tx*4];
            const float qa[4] = {qf.x, qf.y, qf.z, qf.w};
            const float ka[4] = {kf.x, kf.y, kf.z, kf.w};
#pragma unroll
            for (int i = 0; i < 4; i++)
#pragma unroll
                for (int j = 0; j < 4; j++)
                    s[i][j] = fmaf(qa[i], ka[j], s[i][j]);
        }
        __syncthreads();

        float p[4][4];
#pragma unroll
        for (int i = 0; i < 4; i++) {
            const int r = m0 + ty*4 + i;
            float sv[4];
            float rm = -1e30f;
#pragma unroll
            for (int j = 0; j < 4; j++) {
                const int c = n0 + tx*4 + j;
                float val = s[i][j] * scale + slope * (float)(c - r);
                bool valid = (c <= r) && (c >= r - WIN_);
                sv[j] = valid ? val : -1e30f;
                rm = fmaxf(rm, sv[j]);
            }
#pragma unroll
            for (int o = 1; o < 16; o <<= 1)
                rm = fmaxf(rm, __shfl_xor_sync(0xffffffffu, rm, o));
            const float nm    = fmaxf(mrow[i], rm);
            const float alpha = __expf(mrow[i] - nm);
            float rs = 0.f;
#pragma unroll
            for (int j = 0; j < 4; j++) {
                float pv = (sv[j] > -1e29f) ? __expf(sv[j] - nm) : 0.f;
                p[i][j] = pv; rs += pv;
            }
#pragma unroll
            for (int o = 1; o < 16; o <<= 1)
                rs += __shfl_xor_sync(0xffffffffu, rs, o);
            lrow[i] = lrow[i] * alpha + rs;
            mrow[i] = nm;
#pragma unroll
            for (int j = 0; j < 4; j++) acc[i][j] *= alpha;
        }

#pragma unroll
        for (int i = 0; i < 4; i++)
            *(float4*)&KP[ty*4 + i][tx*4] =
                make_float4(p[i][0], p[i][1], p[i][2], p[i][3]);
        __syncthreads();

        for (int c0 = 0; c0 < 64; c0 += 4) {
            float4 pf[4], vf[4];
#pragma unroll
            for (int i = 0; i < 4; i++)  pf[i] = *(const float4*)&KP[ty*4 + i][c0];
#pragma unroll
            for (int cc = 0; cc < 4; cc++) vf[cc] = *(const float4*)&Vs[c0 + cc][tx*4];
#pragma unroll
            for (int i = 0; i < 4; i++) {
                const float pa[4] = {pf[i].x, pf[i].y, pf[i].z, pf[i].w};
#pragma unroll
                for (int cc = 0; cc < 4; cc++) {
                    const float va[4] = {vf[cc].x, vf[cc].y, vf[cc].z, vf[cc].w};
#pragma unroll
                    for (int j = 0; j < 4; j++)
                        acc[i][j] = fmaf(pa[cc], va[j], acc[i][j]);
                }
            }
        }
    }

#pragma unroll
    for (int i = 0; i < 4; i++) {
        const float inv = 1.f / lrow[i];
        float* op = g_ao + base + (size_t)(m0 + ty*4 + i) * D_ + tx*4;
        *(float4*)op = make_float4(acc[i][0]*inv, acc[i][1]*inv,
                                   acc[i][2]*inv, acc[i][3]*inv);
    }
}

// ---------------------------------------------------------------------------
extern "C" void kernel_launch(void* const* d_in, const int* in_sizes, int n_in,
                              void* d_out, int out_size)
{
    const float* x  = (const float*)d_in[0];
    const float* wq = (const float*)d_in[1];
    const float* wk = (const float*)d_in[2];
    const float* wv = (const float*)d_in[3];
    const float* wo = (const float*)d_in[4];
    const float* qw = (const float*)d_in[5];
    const float* kw = (const float*)d_in[6];
    float* out = (float*)d_out;

    float *q_, *k_, *v_, *ao;
    cudaGetSymbolAddress((void**)&q_, g_q);
    cudaGetSymbolAddress((void**)&k_, g_k);
    cudaGetSymbolAddress((void**)&v_, g_v);
    cudaGetSymbolAddress((void**)&ao, g_ao);
    __nv_bfloat16 *xhi, *xlo, *aohi, *aolo, *whi, *wlo;
    cudaGetSymbolAddress((void**)&xhi,  g_xhi);
    cudaGetSymbolAddress((void**)&xlo,  g_xlo);
    cudaGetSymbolAddress((void**)&aohi, g_aohi);
    cudaGetSymbolAddress((void**)&aolo, g_aolo);
    cudaGetSymbolAddress((void**)&whi,  g_whi);
    cudaGetSymbolAddress((void**)&wlo,  g_wlo);

    cudaFuncSetAttribute(gemm_hmma, cudaFuncAttributeMaxDynamicSharedMemorySize,
                         GEMM_SMEM);

    const int nx8 = (B_*T_*D_) / 8;   // 524288
    const int nw8 = (D_*D_) / 8;      // 131072

    cvt_split<<<nx8 / 256, 256>>>(x,  xhi, xlo, nx8);
    cvt_split<<<nw8 / 256, 256>>>(wq, whi + 0*D_*D_, wlo + 0*D_*D_, nw8);
    cvt_split<<<nw8 / 256, 256>>>(wk, whi + 1*D_*D_, wlo + 1*D_*D_, nw8);
    cvt_split<<<nw8 / 256, 256>>>(wv, whi + 2*D_*D_, wlo + 2*D_*D_, nw8);
    cvt_split<<<nw8 / 256, 256>>>(wo, whi + 3*D_*D_, wlo + 3*D_*D_, nw8);

    dim3 gg(D_ / 128, ROWS_ / 128);   // (8, 32)
    gemm_hmma<<<gg, 256, GEMM_SMEM>>>(xhi, xlo, whi + 0*D_*D_, wlo + 0*D_*D_,
                                      q_, ROWS_, D_, D_);
    gemm_hmma<<<gg, 256, GEMM_SMEM>>>(xhi, xlo, whi + 1*D_*D_, wlo + 1*D_*D_,
                                      k_, ROWS_, D_, D_);
    gemm_hmma<<<gg, 256, GEMM_SMEM>>>(xhi, xlo, whi + 2*D_*D_, wlo + 2*D_*D_,
                                      v_, ROWS_, D_, D_);

    rmsnorm_k<<<dim3(ROWS_, 2), 256>>>(qw, kw);
    attn_k<<<dim3(T_ / 64, B_ * H_), 256>>>();

    cvt_split<<<nx8 / 256, 256>>>(ao, aohi, aolo, nx8);
    gemm_hmma<<<gg, 256, GEMM_SMEM>>>(aohi, aolo, whi + 3*D_*D_, wlo + 3*D_*D_,
                                      out, ROWS_, D_, D_);
}

// round 4
// speedup vs baseline: 2.8301x; 1.5732x over previous
#include <cuda_runtime.h>
#include <cuda_bf16.h>
#include <math.h>
#include <stdint.h>

#define B_    2
#define T_    2048
#define D_    1024
#define H_    16
#define HD_   64
#define WIN_  512
#define ROWS_ (B_*T_)   // 4096

// ---------------- scratch (device globals; no runtime alloc) ----------------
__device__ float g_qkv[ROWS_ * 3 * D_];          // fused QKV output (fp32)
__device__ __nv_bfloat16 g_xhi [ROWS_*D_];
__device__ __nv_bfloat16 g_xlo [ROWS_*D_];
__device__ __nv_bfloat16 g_qhi [ROWS_*D_];
__device__ __nv_bfloat16 g_qlo [ROWS_*D_];
__device__ __nv_bfloat16 g_khi [ROWS_*D_];
__device__ __nv_bfloat16 g_klo [ROWS_*D_];
__device__ __nv_bfloat16 g_vhi [ROWS_*D_];
__device__ __nv_bfloat16 g_vlo [ROWS_*D_];
__device__ __nv_bfloat16 g_aohi[ROWS_*D_];
__device__ __nv_bfloat16 g_aolo[ROWS_*D_];
__device__ __nv_bfloat16 g_whi [4 * D_ * D_];    // wq|wk|wv|wo
__device__ __nv_bfloat16 g_wlo [4 * D_ * D_];

__device__ __forceinline__ uint32_t smem_to_u32(const void* p) {
    uint32_t a;
    asm("{ .reg .u64 t; cvta.to.shared.u64 t, %1; cvt.u32.u64 %0, t; }"
        : "=r"(a) : "l"(p));
    return a;
}

#define LDSM4(r, addr) \
    asm volatile("ldmatrix.sync.aligned.m8n8.x4.shared.b16 {%0,%1,%2,%3}, [%4];" \
        : "=r"((r)[0]), "=r"((r)[1]), "=r"((r)[2]), "=r"((r)[3]) : "r"(addr))
#define LDSM4T(r, addr) \
    asm volatile("ldmatrix.sync.aligned.m8n8.x4.trans.shared.b16 {%0,%1,%2,%3}, [%4];" \
        : "=r"((r)[0]), "=r"((r)[1]), "=r"((r)[2]), "=r"((r)[3]) : "r"(addr))

#define MMA_BF16(c, a, b0, b1) \
    asm volatile("mma.sync.aligned.m16n8k16.row.col.f32.bf16.bf16.f32 " \
        "{%0,%1,%2,%3}, {%4,%5,%6,%7}, {%8,%9}, {%0,%1,%2,%3};" \
        : "+f"((c)[0]), "+f"((c)[1]), "+f"((c)[2]), "+f"((c)[3]) \
        : "r"((a)[0]), "r"((a)[1]), "r"((a)[2]), "r"((a)[3]), "r"(b0), "r"(b1))

#define CP_ASYNC16(sa, gp) \
    asm volatile("cp.async.cg.shared.global [%0], [%1], 16;\n" :: "r"(sa), "l"(gp))
#define CP_COMMIT()  asm volatile("cp.async.commit_group;\n" ::: "memory")
#define CP_WAIT(n)   asm volatile("cp.async.wait_group %0;\n" :: "n"(n) : "memory")

__device__ __forceinline__ uint32_t pack_bf16x2(float lo, float hi) {
    union { __nv_bfloat162 h; uint32_t u; } t;
    t.h = __float22bfloat162_rn(make_float2(lo, hi));
    return t.u;
}

// ---------------------------------------------------------------------------
// fp32 -> (bf16 hi, bf16 lo) split (for x)
// ---------------------------------------------------------------------------
__global__ __launch_bounds__(256) void cvt_split(const float* __restrict__ in,
                                                 __nv_bfloat16* __restrict__ hi,
                                                 __nv_bfloat16* __restrict__ lo,
                                                 int n8)
{
    int u = blockIdx.x * 256 + threadIdx.x;
    if (u >= n8) return;
    const float4* p = (const float4*)in + (size_t)u * 2;
    float4 a = p[0], b = p[1];
    float f[8] = {a.x, a.y, a.z, a.w, b.x, b.y, b.z, b.w};
    union { __nv_bfloat16 h[8]; uint4 u4; } ph, pl;
#pragma unroll
    for (int j = 0; j < 8; j++) {
        __nv_bfloat16 h = __float2bfloat16_rn(f[j]);
        float r = f[j] - __bfloat162float(h);
        ph.h[j] = h;
        pl.h[j] = __float2bfloat16_rn(r);
    }
    *(uint4*)(hi + (size_t)u * 8) = ph.u4;
    *(uint4*)(lo + (size_t)u * 8) = pl.u4;
}

// all 4 weights in one launch (blockIdx.y selects weight)
__global__ __launch_bounds__(256) void cvt_w(const float* __restrict__ w0,
                                             const float* __restrict__ w1,
                                             const float* __restrict__ w2,
                                             const float* __restrict__ w3)
{
    const int wsel = blockIdx.y;
    const float* src = (wsel == 0) ? w0 : (wsel == 1) ? w1 : (wsel == 2) ? w2 : w3;
    __nv_bfloat16* hi = g_whi + (size_t)wsel * D_ * D_;
    __nv_bfloat16* lo = g_wlo + (size_t)wsel * D_ * D_;
    int u = blockIdx.x * 256 + threadIdx.x;
    const float4* p = (const float4*)src + (size_t)u * 2;
    float4 a = p[0], b = p[1];
    float f[8] = {a.x, a.y, a.z, a.w, b.x, b.y, b.z, b.w};
    union { __nv_bfloat16 h[8]; uint4 u4; } ph, pl;
#pragma unroll
    for (int j = 0; j < 8; j++) {
        __nv_bfloat16 h = __float2bfloat16_rn(f[j]);
        float r = f[j] - __bfloat162float(h);
        ph.h[j] = h;
        pl.h[j] = __float2bfloat16_rn(r);
    }
    *(uint4*)(hi + (size_t)u * 8) = ph.u4;
    *(uint4*)(lo + (size_t)u * 8) = pl.u4;
}

// ---------------------------------------------------------------------------
// HMMA bf16 split GEMM: C[M,N] f32 = (Ahi+Alo)[M,K] @ (Whi+Wlo)[N,K]^T
// ---------------------------------------------------------------------------
#define TILE_B   10240          // 128 * 80
#define STAGE_B  40960
#define GEMM_SMEM (2 * STAGE_B)

__global__ __launch_bounds__(256) void gemm_hmma(
    const __nv_bfloat16* __restrict__ Ahi, const __nv_bfloat16* __restrict__ Alo,
    const __nv_bfloat16* __restrict__ Whi, const __nv_bfloat16* __restrict__ Wlo,
    float* __restrict__ C, int M, int N, int K)
{
    extern __shared__ char smem[];
    const uint32_t sb = smem_to_u32(smem);
    const int tid  = threadIdx.x;
    const int lane = tid & 31;
    const int wid  = tid >> 5;
    const int wm   = (wid & 1) * 64;
    const int wn   = (wid >> 1) * 32;
    const int m0   = blockIdx.y * 128;
    const int n0   = blockIdx.x * 128;
    const int NCH  = K >> 5;

    const __nv_bfloat16* srcs[4] = {Ahi, Alo, Whi, Wlo};

    auto issue = [&](int ch, int stg) {
        const int k0 = ch << 5;
        const uint32_t base = sb + (uint32_t)stg * STAGE_B;
#pragma unroll
        for (int t = 0; t < 4; t++) {
            const __nv_bfloat16* src = srcs[t];
            const int rb = (t < 2) ? m0 : n0;
#pragma unroll
            for (int it = 0; it < 2; it++) {
                const int u   = tid + it * 256;
                const int row = u >> 2;
                const int kq  = (u & 3) * 8;
                const uint32_t sa = base + (uint32_t)(t * TILE_B + row * 80 + kq * 2);
                CP_ASYNC16(sa, src + (size_t)(rb + row) * K + k0 + kq);
            }
        }
        CP_COMMIT();
    };

    float acc[4][4][4];
#pragma unroll
    for (int mt = 0; mt < 4; mt++)
#pragma unroll
        for (int nt = 0; nt < 4; nt++)
#pragma unroll
            for (int e = 0; e < 4; e++) acc[mt][nt][e] = 0.f;

    issue(0, 0);

    for (int i = 0; i < NCH; i++) {
        if (i + 1 < NCH) { issue(i + 1, (i + 1) & 1); CP_WAIT(1); }
        else             { CP_WAIT(0); }
        __syncthreads();

        const uint32_t base = sb + (uint32_t)(i & 1) * STAGE_B;
        const uint32_t aH = base, aL = base + TILE_B;
        const uint32_t wH = base + 2 * TILE_B, wL = base + 3 * TILE_B;

#pragma unroll
        for (int ks = 0; ks < 2; ks++) {
            const int kb = ks * 16;
            uint32_t ah[4][4], al[4][4], bh[2][4], bl[2][4];
            const uint32_t aOff = (uint32_t)((wm + (lane & 15)) * 80
                                             + (kb + (lane >> 4) * 8) * 2);
#pragma unroll
            for (int mt = 0; mt < 4; mt++) {
                LDSM4(ah[mt], aH + aOff + mt * 16 * 80);
                LDSM4(al[mt], aL + aOff + mt * 16 * 80);
            }
            const uint32_t bOff = (uint32_t)((wn + ((lane >> 4) * 8) + (lane & 7)) * 80
                                             + (kb + ((lane >> 3) & 1) * 8) * 2);
#pragma unroll
            for (int p = 0; p < 2; p++) {
                LDSM4(bh[p], wH + bOff + p * 16 * 80);
                LDSM4(bl[p], wL + bOff + p * 16 * 80);
            }
#pragma unroll
            for (int mt = 0; mt < 4; mt++)
#pragma unroll
                for (int nt = 0; nt < 4; nt++) {
                    const int p = nt >> 1, s = (nt & 1) * 2;
                    MMA_BF16(acc[mt][nt], ah[mt], bh[p][s], bh[p][s + 1]);
                    MMA_BF16(acc[mt][nt], ah[mt], bl[p][s], bl[p][s + 1]);
                    MMA_BF16(acc[mt][nt], al[mt], bh[p][s], bh[p][s + 1]);
                }
        }
        __syncthreads();
    }

#pragma unroll
    for (int mt = 0; mt < 4; mt++)
#pragma unroll
        for (int nt = 0; nt < 4; nt++) {
            const int r = m0 + wm + mt * 16 + (lane >> 2);
            const int c = n0 + wn + nt * 8 + (lane & 3) * 2;
            *(float2*)(C + (size_t)r * N + c) =
                make_float2(acc[mt][nt][0], acc[mt][nt][1]);
            *(float2*)(C + (size_t)(r + 8) * N + c) =
                make_float2(acc[mt][nt][2], acc[mt][nt][3]);
        }
}

// ---------------------------------------------------------------------------
// RMSNorm (q,k full-row) + bf16 hi/lo split of q,k,v from fused qkv buffer.
// One block per token row.
// ---------------------------------------------------------------------------
__global__ __launch_bounds__(256) void rms_split(const float* __restrict__ qw,
                                                 const float* __restrict__ kw)
{
    const int row = blockIdx.x;
    const int tid = threadIdx.x;
    const float* base = g_qkv + (size_t)row * 3 * D_;
    float4 qv = ((const float4*)(base        ))[tid];
    float4 kv = ((const float4*)(base +   D_))[tid];
    float4 vv = ((const float4*)(base + 2*D_))[tid];

    float sq = qv.x*qv.x + qv.y*qv.y + qv.z*qv.z + qv.w*qv.w;
    float sk = kv.x*kv.x + kv.y*kv.y + kv.z*kv.z + kv.w*kv.w;
#pragma unroll
    for (int o = 16; o > 0; o >>= 1) {
        sq += __shfl_xor_sync(0xffffffffu, sq, o);
        sk += __shfl_xor_sync(0xffffffffu, sk, o);
    }
    __shared__ float rq[8], rk[8];
    if ((tid & 31) == 0) { rq[tid >> 5] = sq; rk[tid >> 5] = sk; }
    __syncthreads();
    float tq = rq[0]+rq[1]+rq[2]+rq[3]+rq[4]+rq[5]+rq[6]+rq[7];
    float tk = rk[0]+rk[1]+rk[2]+rk[3]+rk[4]+rk[5]+rk[6]+rk[7];
    const float iq = rsqrtf(tq * (1.f / D_) + 1e-6f);
    const float ik = rsqrtf(tk * (1.f / D_) + 1e-6f);

    float4 qwv = ((const float4*)qw)[tid];
    float4 kwv = ((const float4*)kw)[tid];
    float qf[4] = {qv.x*iq*qwv.x, qv.y*iq*qwv.y, qv.z*iq*qwv.z, qv.w*iq*qwv.w};
    float kf[4] = {kv.x*ik*kwv.x, kv.y*ik*kwv.y, kv.z*ik*kwv.z, kv.w*ik*kwv.w};
    float vf[4] = {vv.x, vv.y, vv.z, vv.w};

    union { __nv_bfloat16 h[4]; uint2 u2; } o1, o2;
    const size_t idx = (size_t)row * D_ + tid * 4;
#pragma unroll
    for (int j = 0; j < 4; j++) {
        __nv_bfloat16 h = __float2bfloat16_rn(qf[j]);
        o1.h[j] = h; o2.h[j] = __float2bfloat16_rn(qf[j] - __bfloat162float(h));
    }
    *(uint2*)(g_qhi + idx) = o1.u2; *(uint2*)(g_qlo + idx) = o2.u2;
#pragma unroll
    for (int j = 0; j < 4; j++) {
        __nv_bfloat16 h = __float2bfloat16_rn(kf[j]);
        o1.h[j] = h; o2.h[j] = __float2bfloat16_rn(kf[j] - __bfloat162float(h));
    }
    *(uint2*)(g_khi + idx) = o1.u2; *(uint2*)(g_klo + idx) = o2.u2;
#pragma unroll
    for (int j = 0; j < 4; j++) {
        __nv_bfloat16 h = __float2bfloat16_rn(vf[j]);
        o1.h[j] = h; o2.h[j] = __float2bfloat16_rn(vf[j] - __bfloat162float(h));
    }
    *(uint2*)(g_vhi + idx) = o1.u2; *(uint2*)(g_vlo + idx) = o2.u2;
}

// ---------------------------------------------------------------------------
// HMMA flash attention, windowed causal + ALiBi, hi/lo bf16 split.
// CTA: 128 threads (4 warps x 16 rows), 64-row q tile, 64-key blocks.
// smem rows padded to 72 bf16 (144 B, 9x16B -> ldmatrix conflict-free).
// ---------------------------------------------------------------------------
#define AT_RB   144                 // row bytes
#define AT_TILE (64 * AT_RB)        // 9216
#define SM_QH   0
#define SM_QL   (1 * AT_TILE)
#define SM_KH   (2 * AT_TILE)
#define SM_KL   (3 * AT_TILE)
#define SM_VH   (4 * AT_TILE)
#define SM_VL   (5 * AT_TILE)
#define ATTN_SMEM (6 * AT_TILE)     // 55296

__global__ __launch_bounds__(128) void attn_mma()
{
    extern __shared__ char smem[];
    const uint32_t sb = smem_to_u32(smem);
    const int tid  = threadIdx.x;
    const int lane = tid & 31;
    const int wid  = tid >> 5;
    const int b    = blockIdx.y >> 4;
    const int h    = blockIdx.y & 15;
    const int m0   = blockIdx.x * 64;
    const float slope = exp2f(-0.5f * (float)(h + 1));
    const float scale = 0.125f;
    const size_t rowbase = (size_t)b * T_;     // token row offset
    const int    hc      = h * HD_;            // head column offset

    // ---- load Q tile (hi+lo): 64 rows x 128B each ----
    for (int u = tid; u < 512; u += 128) {
        const int r = u >> 3, c = u & 7;
        const size_t g = (rowbase + m0 + r) * D_ + hc + c * 8;
        const uint32_t so = (uint32_t)(r * AT_RB + c * 16);
        CP_ASYNC16(sb + SM_QH + so, g_qhi + g);
        CP_ASYNC16(sb + SM_QL + so, g_qlo + g);
    }
    CP_COMMIT();

    float o[8][4];
    float mrow[2] = {-1e30f, -1e30f}, lrow[2] = {0.f, 0.f};
#pragma unroll
    for (int nf = 0; nf < 8; nf++)
#pragma unroll
        for (int e = 0; e < 4; e++) o[nf][e] = 0.f;

    const int jb0 = max(0, m0 - WIN_) >> 6;
    const int jb1 = m0 >> 6;

    const int r0a = m0 + wid * 16 + (lane >> 2);   // this thread's low row
    const int col4 = (lane & 3) * 2;

    for (int jb = jb0; jb <= jb1; jb++) {
        const int n0 = jb << 6;
        __syncthreads();   // prior iter done with K/V smem
        for (int u = tid; u < 512; u += 128) {
            const int r = u >> 3, c = u & 7;
            const size_t g = (rowbase + n0 + r) * D_ + hc + c * 8;
            const uint32_t so = (uint32_t)(r * AT_RB + c * 16);
            CP_ASYNC16(sb + SM_KH + so, g_khi + g);
            CP_ASYNC16(sb + SM_KL + so, g_klo + g);
            CP_ASYNC16(sb + SM_VH + so, g_vhi + g);
            CP_ASYNC16(sb + SM_VL + so, g_vlo + g);
        }
        CP_COMMIT();
        CP_WAIT(0);
        __syncthreads();

        // ---- S = Q K^T (hi/lo split) ----
        float s[8][4];
#pragma unroll
        for (int nf = 0; nf < 8; nf++)
#pragma unroll
            for (int e = 0; e < 4; e++) s[nf][e] = 0.f;

#pragma unroll
        for (int kb = 0; kb < 4; kb++) {
            uint32_t qh4[4], ql4[4];
            const uint32_t aOff = (uint32_t)((wid * 16 + (lane & 15)) * AT_RB
                                             + (kb * 16 + (lane >> 4) * 8) * 2);
            LDSM4(qh4, sb + SM_QH + aOff);
            LDSM4(ql4, sb + SM_QL + aOff);
            const uint32_t bOff = (uint32_t)((((lane >> 4) * 8) + (lane & 7)) * AT_RB
                                             + (kb * 16 + ((lane >> 3) & 1) * 8) * 2);
#pragma unroll
            for (int g = 0; g < 4; g++) {
                uint32_t kh4[4], kl4[4];
                LDSM4(kh4, sb + SM_KH + bOff + g * 16 * AT_RB);
                LDSM4(kl4, sb + SM_KL + bOff + g * 16 * AT_RB);
                MMA_BF16(s[2*g],   qh4, kh4[0], kh4[1]);
                MMA_BF16(s[2*g],   qh4, kl4[0], kl4[1]);
                MMA_BF16(s[2*g],   ql4, kh4[0], kh4[1]);
                MMA_BF16(s[2*g+1], qh4, kh4[2], kh4[3]);
                MMA_BF16(s[2*g+1], qh4, kl4[2], kl4[3]);
                MMA_BF16(s[2*g+1], ql4, kh4[2], kh4[3]);
            }
        }

        // ---- softmax (online) ----
        float mx[2] = {-1e30f, -1e30f};
#pragma unroll
        for (int nf = 0; nf < 8; nf++) {
#pragma unroll
            for (int t = 0; t < 2; t++) {
                const int r = r0a + t * 8;
#pragma unroll
                for (int j = 0; j < 2; j++) {
                    const int c = n0 + nf * 8 + col4 + j;
                    float val = s[nf][2*t + j] * scale + slope * (float)(c - r);
                    const bool valid = (c <= r) && (c >= r - WIN_);
                    val = valid ? val : -1e30f;
                    s[nf][2*t + j] = val;
                    mx[t] = fmaxf(mx[t], val);
                }
            }
        }
#pragma unroll
        for (int t = 0; t < 2; t++) {
            mx[t] = fmaxf(mx[t], __shfl_xor_sync(0xffffffffu, mx[t], 1));
            mx[t] = fmaxf(mx[t], __shfl_xor_sync(0xffffffffu, mx[t], 2));
        }
        float nm[2], alpha[2], rs[2] = {0.f, 0.f};
#pragma unroll
        for (int t = 0; t < 2; t++) {
            nm[t]    = fmaxf(mrow[t], mx[t]);
            alpha[t] = __expf(mrow[t] - nm[t]);
        }
#pragma unroll
        for (int nf = 0; nf < 8; nf++)
#pragma unroll
            for (int t = 0; t < 2; t++)
#pragma unroll
                for (int j = 0; j < 2; j++) {
                    const float v = s[nf][2*t + j];
                    const float p = (v > -1e29f) ? __expf(v - nm[t]) : 0.f;
                    s[nf][2*t + j] = p;
                    rs[t] += p;
                }
#pragma unroll
        for (int t = 0; t < 2; t++) {
            rs[t] += __shfl_xor_sync(0xffffffffu, rs[t], 1);
            rs[t] += __shfl_xor_sync(0xffffffffu, rs[t], 2);
            lrow[t] = lrow[t] * alpha[t] + rs[t];
            mrow[t] = nm[t];
        }
#pragma unroll
        for (int nf = 0; nf < 8; nf++) {
            o[nf][0] *= alpha[0]; o[nf][1] *= alpha[0];
            o[nf][2] *= alpha[1]; o[nf][3] *= alpha[1];
        }

        // ---- pack P into bf16 hi/lo A-fragments ----
        uint32_t ph[4][4], pl[4][4];
#pragma unroll
        for (int kf = 0; kf < 4; kf++) {
            const int f0 = 2 * kf, f1 = 2 * kf + 1;
            const float e[8] = {s[f0][0], s[f0][1], s[f0][2], s[f0][3],
                                s[f1][0], s[f1][1], s[f1][2], s[f1][3]};
#pragma unroll
            for (int q = 0; q < 4; q++) {
                const float a0 = e[q*2], a1 = e[q*2+1];
                uint32_t hi = pack_bf16x2(a0, a1);
                union { uint32_t u; __nv_bfloat162 h; } t; t.u = hi;
                float2 hf = __bfloat1622float2(t.h);
                ph[kf][q] = hi;
                pl[kf][q] = pack_bf16x2(a0 - hf.x, a1 - hf.y);
            }
        }

        // ---- O += P V (hi/lo split, V via ldmatrix.trans) ----
#pragma unroll
        for (int kf = 0; kf < 4; kf++) {
            const uint32_t vRow = (uint32_t)((kf * 16 + ((lane >> 4) * 8) + (lane & 7)) * AT_RB);
            const uint32_t vCol = (uint32_t)((((lane >> 3) & 1) * 8) * 2);
#pragma unroll
            for (int g = 0; g < 4; g++) {
                uint32_t vh4[4], vl4[4];
                const uint32_t va = vRow + vCol + (uint32_t)(g * 32);
                LDSM4T(vh4, sb + SM_VH + va);
                LDSM4T(vl4, sb + SM_VL + va);
                MMA_BF16(o[2*g],   ph[kf], vh4[0], vh4[2]);
                MMA_BF16(o[2*g],   pl[kf], vh4[0], vh4[2]);
                MMA_BF16(o[2*g],   ph[kf], vl4[0], vl4[2]);
                MMA_BF16(o[2*g+1], ph[kf], vh4[1], vh4[3]);
                MMA_BF16(o[2*g+1], pl[kf], vh4[1], vh4[3]);
                MMA_BF16(o[2*g+1], ph[kf], vl4[1], vl4[3]);
            }
        }
    }

    // ---- epilogue: normalize, split to bf16 hi/lo, store ----
#pragma unroll
    for (int t = 0; t < 2; t++) {
        const int r = r0a + t * 8;
        const float inv = 1.f / lrow[t];
#pragma unroll
        for (int nf = 0; nf < 8; nf++) {
            const float x0 = o[nf][2*t]     * inv;
            const float x1 = o[nf][2*t + 1] * inv;
            const uint32_t hi = pack_bf16x2(x0, x1);
            union { uint32_t u; __nv_bfloat162 h; } w; w.u = hi;
            float2 hf = __bfloat1622float2(w.h);
            const uint32_t lo = pack_bf16x2(x0 - hf.x, x1 - hf.y);
            const size_t g = (rowbase + r) * D_ + hc + nf * 8 + col4;
            *(uint32_t*)(g_aohi + g) = hi;
            *(uint32_t*)(g_aolo + g) = lo;
        }
    }
}

// ---------------------------------------------------------------------------
extern "C" void kernel_launch(void* const* d_in, const int* in_sizes, int n_in,
                              void* d_out, int out_size)
{
    const float* x  = (const float*)d_in[0];
    const float* wq = (const float*)d_in[1];
    const float* wk = (const float*)d_in[2];
    const float* wv = (const float*)d_in[3];
    const float* wo = (const float*)d_in[4];
    const float* qw = (const float*)d_in[5];
    const float* kw = (const float*)d_in[6];
    float* out = (float*)d_out;

    float* qkv;
    cudaGetSymbolAddress((void**)&qkv, g_qkv);
    __nv_bfloat16 *xhi, *xlo, *aohi, *aolo, *whi, *wlo;
    cudaGetSymbolAddress((void**)&xhi,  g_xhi);
    cudaGetSymbolAddress((void**)&xlo,  g_xlo);
    cudaGetSymbolAddress((void**)&aohi, g_aohi);
    cudaGetSymbolAddress((void**)&aolo, g_aolo);
    cudaGetSymbolAddress((void**)&whi,  g_whi);
    cudaGetSymbolAddress((void**)&wlo,  g_wlo);

    cudaFuncSetAttribute(gemm_hmma, cudaFuncAttributeMaxDynamicSharedMemorySize,
                         GEMM_SMEM);
    cudaFuncSetAttribute(attn_mma, cudaFuncAttributeMaxDynamicSharedMemorySize,
                         ATTN_SMEM);

    const int nx8 = (ROWS_*D_) / 8;   // 524288
    const int nw8 = (D_*D_) / 8;      // 131072

    cvt_split<<<nx8 / 256, 256>>>(x, xhi, xlo, nx8);
    cvt_w<<<dim3(nw8 / 256, 4), 256>>>(wq, wk, wv, wo);

    // fused QKV projection: [4096,1024] @ [3072,1024]^T -> [4096,3072]
    gemm_hmma<<<dim3(3*D_/128, ROWS_/128), 256, GEMM_SMEM>>>(
        xhi, xlo, whi, wlo, qkv, ROWS_, 3*D_, D_);

    rms_split<<<ROWS_, 256>>>(qw, kw);

    attn_mma<<<dim3(T_/64, B_*H_), 128, ATTN_SMEM>>>();

    // output projection
    gemm_hmma<<<dim3(D_/128, ROWS_/128), 256, GEMM_SMEM>>>(
        aohi, aolo, whi + 3*(size_t)D_*D_, wlo + 3*(size_t)D_*D_,
        out, ROWS_, D_, D_);
}